// round 9
// baseline (speedup 1.0000x reference)
#include <cuda_runtime.h>

#define NSAMP 65536
#define EPSF 1e-8f
#define BLOCK_THREADS 128
#define NBLOCKS 888                    // 6 CTAs/SM x 148 SMs: single resident wave
#define PAIRS_PER_CTA 2
#define TOTAL_PAIRS (NBLOCKS * PAIRS_PER_CTA)

// Two warps per sample. Warp h in {0,1} owns i-half h.
// Lane l -> (o = l>>1, j = l&1); lane owns pairs (o, i = h*8 + j*4 + k), k=0..3.
// Softmax-over-o is warp-local (all 16 o in-warp). Only the 4-float s-sum
// crosses warps: STS.128 + named barrier (pair-scoped) + LDS.128, double-buffered.

__device__ __forceinline__ float fastrcp(float d) {
    float r;
    asm("rcp.approx.f32 %0, %1;" : "=f"(r) : "f"(d));
    return r;
}

__global__ void __launch_bounds__(BLOCK_THREADS, 6)
caps_quat_kernel(const float* __restrict__ x,
                 const float* __restrict__ quats,
                 const float* __restrict__ scale,
                 const float* __restrict__ trans,
                 const float* __restrict__ bias,
                 const float* __restrict__ beta,
                 const float* __restrict__ alpha,
                 float* __restrict__ out)
{
    __shared__ float4 sS[2][PAIRS_PER_CTA][2][16];   // [buf][pair][h][o]

    const int tid       = threadIdx.x;
    const int lane      = tid & 31;
    const int warpInCta = tid >> 5;
    const int pairInCta = warpInCta >> 1;
    const int h         = warpInCta & 1;       // i-half owned by this warp
    const int j         = lane & 1;            // i-quarter within half
    const int o         = lane >> 1;           // output capsule
    const int barId     = pairInCta + 1;

    // ---- prologue: scaled quaternion + trans for this lane's 4 pairs ----
    float qw[4], qx[4], qy[4], qz[4], t1[4], t2[4], t3[4];
    const float4* __restrict__ q4 = (const float4*)quats;
#pragma unroll
    for (int k = 0; k < 4; k++) {
        const int pi = o * 16 + h * 8 + j * 4 + k;
        const float4 q = __ldg(&q4[pi]);
        const float f = rsqrtf(fmaf(q.x, q.x, fmaf(q.y, q.y, fmaf(q.z, q.z, q.w * q.w))) + EPSF)
                        * __ldg(&scale[pi]);
        qw[k] = q.x * f; qx[k] = q.y * f; qy[k] = q.z * f; qz[k] = q.w * f;
        t1[k] = __ldg(&trans[pi * 3 + 0]);
        t2[k] = __ldg(&trans[pi * 3 + 1]);
        t3[k] = __ldg(&trans[pi * 3 + 2]);
    }
    const float bet = __ldg(&beta[o]);
    const float ab  = __ldg(&alpha[o]) + __ldg(&bias[o]);

    const float4* __restrict__ x4   = (const float4*)x;
    float4* __restrict__       out4 = (float4*)out;

    const int pairId = blockIdx.x * PAIRS_PER_CTA + pairInCta;
    const bool b8  = (lane & 8)  != 0;
    const bool b16 = (lane & 16) != 0;

#pragma unroll 1
    for (int n = pairId; n < NSAMP; n += TOTAL_PAIRS) {
        // ---- votes: 4 per lane (this warp's i-half) ----
        float vw[4], vx[4], vy[4], vz[4];
#pragma unroll
        for (int k = 0; k < 4; k++) {
            const float4 X = __ldg(&x4[n * 16 + h * 8 + j * 4 + k]);
            vw[k] = fmaf(qw[k], X.x, fmaf(-qx[k], X.y, fmaf(-qy[k], X.z, -qz[k] * X.w)));
            vx[k] = fmaf(qw[k], X.y, fmaf( qx[k], X.x, fmaf( qy[k], X.w, fmaf(-qz[k], X.z, t1[k]))));
            vy[k] = fmaf(qw[k], X.z, fmaf(-qx[k], X.w, fmaf( qy[k], X.x, fmaf( qz[k], X.y, t2[k]))));
            vz[k] = fmaf(qw[k], X.w, fmaf( qx[k], X.z, fmaf(-qy[k], X.y, fmaf( qz[k], X.x, t3[k]))));
        }

        float bb[4];
        float s0, s1, s2, s3, v0, v1, v2, v3, n2 = 0.0f;

#pragma unroll
        for (int iter = 0; iter < 3; iter++) {
            if (iter == 0) {
                // uniform coupling c = 1/16
                s0 = vw[0] + vw[1] + vw[2] + vw[3];
                s1 = vx[0] + vx[1] + vx[2] + vx[3];
                s2 = vy[0] + vy[1] + vy[2] + vy[3];
                s3 = vz[0] + vz[1] + vz[2] + vz[3];
                s0 *= 0.0625f; s1 *= 0.0625f; s2 *= 0.0625f; s3 *= 0.0625f;
            } else {
                // softmax over o — warp-local (all 16 o in this warp).
                float e[4], r[4];
#pragma unroll
                for (int k = 0; k < 4; k++) { e[k] = __expf(bb[k]); r[k] = e[k]; }

                // reduce-scatter over o-lanes: masks 16 (4->2), 8 (2->1)
#pragma unroll
                for (int kk = 0; kk < 2; kk++) {
                    const float snd = b16 ? r[kk] : r[kk + 2];
                    const float rcv = __shfl_xor_sync(0xffffffffu, snd, 16);
                    r[kk] = (b16 ? r[kk + 2] : r[kk]) + rcv;
                }
                {
                    const float snd = b8 ? r[0] : r[1];
                    const float rcv = __shfl_xor_sync(0xffffffffu, snd, 8);
                    r[0] = (b8 ? r[1] : r[0]) + rcv;
                }
                // finish sum over remaining o bits: plain butterflies (masks 4, 2)
                r[0] += __shfl_xor_sync(0xffffffffu, r[0], 4);
                r[0] += __shfl_xor_sync(0xffffffffu, r[0], 2);

                // lane holds den for k* = 2*b16 + b8 ; one reciprocal
                const float rd = fastrcp(r[0]);

                // all-gather reciprocals: masks 8 then 16
                float rden[4];
                {
                    const float p = __shfl_xor_sync(0xffffffffu, rd, 8);
                    const float g0 = b8 ? p : rd;       // k bit0 = 0
                    const float g1 = b8 ? rd : p;       // k bit0 = 1
                    const float p0 = __shfl_xor_sync(0xffffffffu, g0, 16);
                    const float p1 = __shfl_xor_sync(0xffffffffu, g1, 16);
                    rden[0] = b16 ? p0 : g0;  rden[1] = b16 ? p1 : g1;
                    rden[2] = b16 ? g0 : p0;  rden[3] = b16 ? g1 : p1;
                }

                s0 = s1 = s2 = s3 = 0.0f;
#pragma unroll
                for (int k = 0; k < 4; k++) {
                    const float c = e[k] * rden[k];
                    s0 = fmaf(c, vw[k], s0);
                    s1 = fmaf(c, vx[k], s1);
                    s2 = fmaf(c, vy[k], s2);
                    s3 = fmaf(c, vz[k], s3);
                }
            }

            // fold j-halves within warp
            s0 += __shfl_xor_sync(0xffffffffu, s0, 1);
            s1 += __shfl_xor_sync(0xffffffffu, s1, 1);
            s2 += __shfl_xor_sync(0xffffffffu, s2, 1);
            s3 += __shfl_xor_sync(0xffffffffu, s3, 1);

            // cross-warp fold via shared + named barrier (double-buffered)
            const int buf = iter & 1;
            if (j == 0) {
                sS[buf][pairInCta][h][o] = make_float4(s0, s1, s2, s3);
            }
            asm volatile("bar.sync %0, %1;" :: "r"(barId), "n"(64) : "memory");
            {
                const float4 P = sS[buf][pairInCta][1 - h][o];
                s0 += P.x; s1 += P.y; s2 += P.z; s3 += P.w;
            }

            // squash
            n2 = fmaf(s0, s0, fmaf(s1, s1, fmaf(s2, s2, s3 * s3)));
            const float fac = n2 * fastrcp(1.0f + n2) * rsqrtf(n2 + EPSF);
            v0 = s0 * fac; v1 = s1 * fac; v2 = s2 * fac; v3 = s3 * fac;

            // agreement update (iter0: assignment; dead at iter2)
            if (iter == 0) {
#pragma unroll
                for (int k = 0; k < 4; k++)
                    bb[k] = fmaf(v0, vw[k], fmaf(v1, vx[k], fmaf(v2, vy[k], v3 * vz[k])));
            } else if (iter == 1) {
#pragma unroll
                for (int k = 0; k < 4; k++)
                    bb[k] = fmaf(v0, vw[k], fmaf(v1, vx[k], fmaf(v2, vy[k], fmaf(v3, vz[k], bb[k]))));
            }
        }

        // ---- activation + store (warp h=0, even lanes: one float4 per (n,o)) ----
        const float norm_s = sqrtf(n2 + EPSF);
        const float z = fmaf(bet, norm_s, ab);
        const float a = fastrcp(1.0f + __expf(-z));

        if ((h | j) == 0) {
            out4[n * 16 + o] = make_float4(v0 * a, v1 * a, v2 * a, v3 * a);
        }
    }
}

extern "C" void kernel_launch(void* const* d_in, const int* in_sizes, int n_in,
                              void* d_out, int out_size)
{
    const float* x     = (const float*)d_in[0];
    const float* quats = (const float*)d_in[1];
    const float* scale = (const float*)d_in[2];
    const float* trans = (const float*)d_in[3];
    const float* bias  = (const float*)d_in[4];
    const float* beta  = (const float*)d_in[5];
    const float* alpha = (const float*)d_in[6];

    caps_quat_kernel<<<NBLOCKS, BLOCK_THREADS>>>(x, quats, scale, trans, bias, beta, alpha,
                                                 (float*)d_out);
}

// round 11
// speedup vs baseline: 1.6088x; 1.6088x over previous
#include <cuda_runtime.h>

#define NSAMP 65536
#define EPSF 1e-8f
#define BLOCK_THREADS 128
#define NBLOCKS 592                    // 4 CTAs/SM x 148 SMs: single resident wave
#define TOTAL_WARPS (NBLOCKS * (BLOCK_THREADS / 32))

// Warp-per-sample, register-resident, single-wave persistent kernel.
// Lane l -> (o = l>>1, i-half h = l&1); lane owns pairs (o, i = h*8+k), k=0..7.
// Softmax den: reduce-scatter over o-lanes + single rcp + all-gather (15 shfl).
// Einsum chains tree-shaped; squash factor overlapped with b-update dot products.

__device__ __forceinline__ float fastrcp(float d) {
    float r;
    asm("rcp.approx.f32 %0, %1;" : "=f"(r) : "f"(d));
    return r;
}

__global__ void __launch_bounds__(BLOCK_THREADS, 4)
caps_quat_kernel(const float* __restrict__ x,
                 const float* __restrict__ quats,
                 const float* __restrict__ scale,
                 const float* __restrict__ trans,
                 const float* __restrict__ bias,
                 const float* __restrict__ beta,
                 const float* __restrict__ alpha,
                 float* __restrict__ out)
{
    const int lane = threadIdx.x & 31;
    const int warp = blockIdx.x * (BLOCK_THREADS / 32) + (threadIdx.x >> 5);
    const int h    = lane & 1;       // i-half
    const int o    = lane >> 1;      // output capsule

    // ---- one-time prologue: scaled quaternion + trans for this lane's 8 pairs ----
    float qw[8], qx[8], qy[8], qz[8], t1[8], t2[8], t3[8];
    const float4* __restrict__ q4 = (const float4*)quats;
#pragma unroll
    for (int k = 0; k < 8; k++) {
        const int pi = o * 16 + h * 8 + k;
        const float4 q = __ldg(&q4[pi]);
        const float f = rsqrtf(fmaf(q.x, q.x, fmaf(q.y, q.y, fmaf(q.z, q.z, q.w * q.w))) + EPSF)
                        * __ldg(&scale[pi]);
        qw[k] = q.x * f; qx[k] = q.y * f; qy[k] = q.z * f; qz[k] = q.w * f;
        t1[k] = __ldg(&trans[pi * 3 + 0]);
        t2[k] = __ldg(&trans[pi * 3 + 1]);
        t3[k] = __ldg(&trans[pi * 3 + 2]);
    }
    const float bet = __ldg(&beta[o]);
    const float ab  = __ldg(&alpha[o]) + __ldg(&bias[o]);

    const float4* __restrict__ x4   = (const float4*)x;
    float4* __restrict__       out4 = (float4*)out;

    const bool b4  = (lane & 4)  != 0;
    const bool b8  = (lane & 8)  != 0;
    const bool b16 = (lane & 16) != 0;

#pragma unroll 1
    for (int n = warp; n < NSAMP; n += TOTAL_WARPS) {
        // ---- votes: Hamilton product from quaternion registers ----
        float vw[8], vx[8], vy[8], vz[8];
#pragma unroll
        for (int k = 0; k < 8; k++) {
            const float4 X = __ldg(&x4[n * 16 + h * 8 + k]);
            vw[k] = fmaf(qw[k], X.x, fmaf(-qx[k], X.y, fmaf(-qy[k], X.z, -qz[k] * X.w)));
            vx[k] = fmaf(qw[k], X.y, fmaf( qx[k], X.x, fmaf( qy[k], X.w, fmaf(-qz[k], X.z, t1[k]))));
            vy[k] = fmaf(qw[k], X.z, fmaf(-qx[k], X.w, fmaf( qy[k], X.x, fmaf( qz[k], X.y, t2[k]))));
            vz[k] = fmaf(qw[k], X.w, fmaf( qx[k], X.z, fmaf(-qy[k], X.y, fmaf( qz[k], X.x, t3[k]))));
        }

        // ---- dynamic routing, 3 iterations ----
        float bb[8];
        float s0, s1, s2, s3, v0, v1, v2, v3, n2 = 0.0f;

#pragma unroll
        for (int iter = 0; iter < 3; iter++) {
            if (iter == 0) {
                // b == 0 -> uniform coupling c = 1/16 (tree-shaped sums)
                s0 = (((vw[0] + vw[1]) + (vw[2] + vw[3])) + ((vw[4] + vw[5]) + (vw[6] + vw[7]))) * 0.0625f;
                s1 = (((vx[0] + vx[1]) + (vx[2] + vx[3])) + ((vx[4] + vx[5]) + (vx[6] + vx[7]))) * 0.0625f;
                s2 = (((vy[0] + vy[1]) + (vy[2] + vy[3])) + ((vy[4] + vy[5]) + (vy[6] + vy[7]))) * 0.0625f;
                s3 = (((vz[0] + vz[1]) + (vz[2] + vz[3])) + ((vz[4] + vz[5]) + (vz[6] + vz[7]))) * 0.0625f;
            } else {
                // softmax over o (no max-shift; |b| bounded, f32-safe)
                float e[8], r[8];
#pragma unroll
                for (int k = 0; k < 8; k++) { e[k] = __expf(bb[k]); r[k] = e[k]; }

                // --- reduce-scatter of den over o-lanes (masks 16,8,4,2) ---
#pragma unroll
                for (int j = 0; j < 4; j++) {
                    const float snd = b16 ? r[j] : r[j + 4];
                    const float rcv = __shfl_xor_sync(0xffffffffu, snd, 16);
                    r[j] = (b16 ? r[j + 4] : r[j]) + rcv;
                }
#pragma unroll
                for (int j = 0; j < 2; j++) {
                    const float snd = b8 ? r[j] : r[j + 2];
                    const float rcv = __shfl_xor_sync(0xffffffffu, snd, 8);
                    r[j] = (b8 ? r[j + 2] : r[j]) + rcv;
                }
                {
                    const float snd = b4 ? r[0] : r[1];
                    const float rcv = __shfl_xor_sync(0xffffffffu, snd, 4);
                    r[0] = (b4 ? r[1] : r[0]) + rcv;
                }
                r[0] += __shfl_xor_sync(0xffffffffu, r[0], 2);

                // one reciprocal per lane
                const float rd = fastrcp(r[0]);

                // --- all-gather of reciprocal dens (masks 4,8,16) ---
                float g0, g1, g2, g3, rden[8];
                {
                    const float p = __shfl_xor_sync(0xffffffffu, rd, 4);
                    g0 = b4 ? p : rd;
                    g1 = b4 ? rd : p;
                }
                {
                    const float p0 = __shfl_xor_sync(0xffffffffu, g0, 8);
                    const float p1 = __shfl_xor_sync(0xffffffffu, g1, 8);
                    g2 = b8 ? g0 : p0;  g3 = b8 ? g1 : p1;
                    g0 = b8 ? p0 : g0;  g1 = b8 ? p1 : g1;
                }
                {
                    const float p0 = __shfl_xor_sync(0xffffffffu, g0, 16);
                    const float p1 = __shfl_xor_sync(0xffffffffu, g1, 16);
                    const float p2 = __shfl_xor_sync(0xffffffffu, g2, 16);
                    const float p3 = __shfl_xor_sync(0xffffffffu, g3, 16);
                    rden[0] = b16 ? p0 : g0;  rden[1] = b16 ? p1 : g1;
                    rden[2] = b16 ? p2 : g2;  rden[3] = b16 ? p3 : g3;
                    rden[4] = b16 ? g0 : p0;  rden[5] = b16 ? g1 : p1;
                    rden[6] = b16 ? g2 : p2;  rden[7] = b16 ? g3 : p3;
                }

                float c[8];
#pragma unroll
                for (int k = 0; k < 8; k++) c[k] = e[k] * rden[k];

                // weighted einsum, tree-shaped (depth ~4, 8-way ILP)
                {
                    const float a0 = fmaf(c[1], vw[1], c[0] * vw[0]);
                    const float a1 = fmaf(c[3], vw[3], c[2] * vw[2]);
                    const float a2 = fmaf(c[5], vw[5], c[4] * vw[4]);
                    const float a3 = fmaf(c[7], vw[7], c[6] * vw[6]);
                    s0 = (a0 + a1) + (a2 + a3);
                }
                {
                    const float a0 = fmaf(c[1], vx[1], c[0] * vx[0]);
                    const float a1 = fmaf(c[3], vx[3], c[2] * vx[2]);
                    const float a2 = fmaf(c[5], vx[5], c[4] * vx[4]);
                    const float a3 = fmaf(c[7], vx[7], c[6] * vx[6]);
                    s1 = (a0 + a1) + (a2 + a3);
                }
                {
                    const float a0 = fmaf(c[1], vy[1], c[0] * vy[0]);
                    const float a1 = fmaf(c[3], vy[3], c[2] * vy[2]);
                    const float a2 = fmaf(c[5], vy[5], c[4] * vy[4]);
                    const float a3 = fmaf(c[7], vy[7], c[6] * vy[6]);
                    s2 = (a0 + a1) + (a2 + a3);
                }
                {
                    const float a0 = fmaf(c[1], vz[1], c[0] * vz[0]);
                    const float a1 = fmaf(c[3], vz[3], c[2] * vz[2]);
                    const float a2 = fmaf(c[5], vz[5], c[4] * vz[4]);
                    const float a3 = fmaf(c[7], vz[7], c[6] * vz[6]);
                    s3 = (a0 + a1) + (a2 + a3);
                }
            }
            // fold the two i-halves
            s0 += __shfl_xor_sync(0xffffffffu, s0, 1);
            s1 += __shfl_xor_sync(0xffffffffu, s1, 1);
            s2 += __shfl_xor_sync(0xffffffffu, s2, 1);
            s3 += __shfl_xor_sync(0xffffffffu, s3, 1);

            // squash factor (MUFU chain) ...
            n2 = fmaf(s0, s0, fmaf(s1, s1, fmaf(s2, s2, s3 * s3)));
            const float fac = n2 * fastrcp(1.0f + n2) * rsqrtf(n2 + EPSF);

            // ... overlapped with d[k] = s . vote[k] (independent of fac):
            // bb[k] (+)= fac * d[k]  ==  v . vote[k]
            if (iter == 0) {
#pragma unroll
                for (int k = 0; k < 8; k++) {
                    const float d = fmaf(s0, vw[k], fmaf(s1, vx[k], fmaf(s2, vy[k], s3 * vz[k])));
                    bb[k] = fac * d;
                }
            } else if (iter == 1) {
#pragma unroll
                for (int k = 0; k < 8; k++) {
                    const float d = fmaf(s0, vw[k], fmaf(s1, vx[k], fmaf(s2, vy[k], s3 * vz[k])));
                    bb[k] = fmaf(fac, d, bb[k]);
                }
            }

            v0 = s0 * fac; v1 = s1 * fac; v2 = s2 * fac; v3 = s3 * fac;
        }

        // ---- activation + store (even lanes: one coalesced float4 per (n,o)) ----
        const float norm_s = sqrtf(n2 + EPSF);
        const float z = fmaf(bet, norm_s, ab);
        const float a = fastrcp(1.0f + __expf(-z));

        if (h == 0) {
            out4[n * 16 + o] = make_float4(v0 * a, v1 * a, v2 * a, v3 * a);
        }
    }
}

extern "C" void kernel_launch(void* const* d_in, const int* in_sizes, int n_in,
                              void* d_out, int out_size)
{
    const float* x     = (const float*)d_in[0];
    const float* quats = (const float*)d_in[1];
    const float* scale = (const float*)d_in[2];
    const float* trans = (const float*)d_in[3];
    const float* bias  = (const float*)d_in[4];
    const float* beta  = (const float*)d_in[5];
    const float* alpha = (const float*)d_in[6];

    caps_quat_kernel<<<NBLOCKS, BLOCK_THREADS>>>(x, quats, scale, trans, bias, beta, alpha,
                                                 (float*)d_out);
}